// round 12
// baseline (speedup 1.0000x reference)
#include <cuda_runtime.h>
#include <cstdint>

#define OBS_LEN 20
#define PRED_LEN 30
#define MAXN 131072
#define AG 128
#define K_AUG 36
#define NKT 9
#define BSTR 136   // B operand row stride (floats) — conflict-free
#define GSTR 129   // gates row stride (floats) — conflict-free column reads

typedef unsigned long long u64;
typedef unsigned int u32;

// ---------------- helpers ----------------
__device__ __forceinline__ u64 fma2(u64 a, u64 b, u64 c) {
    u64 d;
    asm("fma.rn.f32x2 %0, %1, %2, %3;" : "=l"(d) : "l"(a), "l"(b), "l"(c));
    return d;
}
__device__ __forceinline__ u64 pack2(float lo, float hi) {
    u64 d;
    asm("mov.b64 %0, {%1, %2};" : "=l"(d) : "f"(lo), "f"(hi));
    return d;
}
__device__ __forceinline__ float2 unpack2(u64 v) {
    float2 r;
    asm("mov.b64 {%0, %1}, %2;" : "=f"(r.x), "=f"(r.y) : "l"(v));
    return r;
}
__device__ __forceinline__ float hsum2(u64 v) { float2 s = unpack2(v); return s.x + s.y; }
__device__ __forceinline__ float tanha(float x) {
    float r;
    asm("tanh.approx.f32 %0, %1;" : "=f"(r) : "f"(x));
    return r;
}
__device__ __forceinline__ float sigt(float x) { return fmaf(0.5f, tanha(0.5f * x), 0.5f); }
__device__ __forceinline__ float to_tf32(float x) {
    u32 u;
    asm("cvt.rna.tf32.f32 %0, %1;" : "=r"(u) : "f"(x));
    return __uint_as_float(u);
}

// classic tensor-core mma (baseline PTX, valid on sm_103 non-a)
__device__ __forceinline__ void mma4(float &d0, float &d1, float &d2, float &d3,
                                     float a0, float a1, float b0)
{
    asm volatile(
        "mma.sync.aligned.m16n8k4.row.col.f32.tf32.tf32.f32 "
        "{%0,%1,%2,%3}, {%4,%5}, {%6}, {%0,%1,%2,%3};"
        : "+f"(d0), "+f"(d1), "+f"(d2), "+f"(d3)
        : "r"(__float_as_uint(a0)), "r"(__float_as_uint(a1)), "r"(__float_as_uint(b0)));
}

// ---------------- scratch ----------------
__device__ float g_h[32 * MAXN];
__device__ float g_d[32 * MAXN];

// smem (floats): Bhi[36][136], Blo[36][136], G[128][129], ow[66]
#define SM_BHI 0
#define SM_BLO (36 * BSTR)
#define SM_G   (2 * 36 * BSTR)
#define SM_OW  (SM_G + 128 * GSTR)
#define SMEM_FLOATS (SM_OW + 72)
#define SMEM_MMA (SMEM_FLOATS * 4)

// ================= MMA LSTM kernel (enc & dec) =================
// xg/xb: enc -> lne_g / lne_b ; dec -> dec_out_w / dec_out_b
template <int STEPS, bool IS_DEC>
__global__ void __launch_bounds__(256, 1)
k_lstm_mma(const float *__restrict__ rel,
           const float *__restrict__ wih, const float *__restrict__ whh,
           const float *__restrict__ bih, const float *__restrict__ bhh,
           const float *__restrict__ embw, const float *__restrict__ embb,
           const float *__restrict__ xg, const float *__restrict__ xb,
           float *__restrict__ out, int n)
{
    extern __shared__ float sm[];
    float *Bhi = sm + SM_BHI;
    float *Blo = sm + SM_BLO;
    float *G = sm + SM_G;
    float *ow = sm + SM_OW;

    const int tid = threadIdx.x;
    const int lane = tid & 31;
    const int w = tid >> 5;          // warp 0..7: owns gate rows [16w, 16w+16)
    const int g = lane >> 2;         // groupID 0..7
    const int t = lane & 3;          // threadID_in_group 0..3
    const int base = blockIdx.x * AG;

    // ---- A fragments (resident in regs): rows r0=16w+g, r1=16w+8+g ----
    float ahi[NKT][2], alo[NKT][2];
#pragma unroll
    for (int rsel = 0; rsel < 2; rsel++) {
        const int r = 16 * w + 8 * rsel + g;
        float w0 = 0.f, w1 = 0.f, b = __ldg(&bih[r]) + __ldg(&bhh[r]);
#pragma unroll
        for (int e = 0; e < 16; e++) {
            float wie = __ldg(&wih[r * 16 + e]);
            w0 = fmaf(wie, __ldg(&embw[e * 2 + 0]), w0);
            w1 = fmaf(wie, __ldg(&embw[e * 2 + 1]), w1);
            b = fmaf(wie, __ldg(&embb[e]), b);
        }
#pragma unroll
        for (int kt = 0; kt < NKT; kt++) {
            const int col = kt * 4 + t;
            float v;
            if (col < 32) v = __ldg(&whh[r * 32 + col]);
            else if (col == 32) v = w0;
            else if (col == 33) v = w1;
            else if (col == 34) v = b;
            else v = 0.f;
            float hi = to_tf32(v);
            ahi[kt][rsel] = hi;
            alo[kt][rsel] = to_tf32(v - hi);
        }
    }

    // ---- init B operand smem ----
    for (int i = tid; i < 36 * BSTR; i += 256) { Bhi[i] = 0.f; Blo[i] = 0.f; }
    __syncthreads();

    const float2 *rel2 = (const float2 *)rel;
    float2 *out2 = (float2 *)out;

    if (tid < 128) {
        const int a = tid;
        Bhi[34 * BSTR + a] = 1.f;                 // ones row (bias)
        if (IS_DEC) {
#pragma unroll
            for (int k = 0; k < 32; k++) {
                float hv = g_d[(size_t)k * n + base + a];
                float hi = to_tf32(hv);
                Bhi[k * BSTR + a] = hi;
                Blo[k * BSTR + a] = to_tf32(hv - hi);
            }
            float2 x = __ldg(&rel2[(size_t)(OBS_LEN - 1) * n + base + a]);
            float xh = to_tf32(x.x);
            Bhi[32 * BSTR + a] = xh; Blo[32 * BSTR + a] = to_tf32(x.x - xh);
            float yh = to_tf32(x.y);
            Bhi[33 * BSTR + a] = yh; Blo[33 * BSTR + a] = to_tf32(x.y - yh);
        } else {
            float2 x = __ldg(&rel2[base + a]);
            float xh = to_tf32(x.x);
            Bhi[32 * BSTR + a] = xh; Blo[32 * BSTR + a] = to_tf32(x.x - xh);
            float yh = to_tf32(x.y);
            Bhi[33 * BSTR + a] = yh; Blo[33 * BSTR + a] = to_tf32(x.y - yh);
        }
    }
    if (IS_DEC) {
        if (tid < 64) ow[tid] = __ldg(&xg[tid]);
        if (tid < 2) ow[64 + tid] = __ldg(&xb[tid]);
    }

    // c state: thread owns cells (j = 4w+jj, a = lane32 + 32*aa) — but note
    // activation mapping below uses j = 4*(w) + jj over 8 warps => j in 0..31.
    float c[16];
#pragma unroll
    for (int i = 0; i < 16; i++) c[i] = 0.f;

    __syncthreads();

#pragma unroll 1
    for (int st = 0; st < STEPS; st++) {
        // ---------- MMA phase: gates[128][128] ----------
#pragma unroll 2
        for (int nt = 0; nt < 16; nt++) {
            float d0 = 0.f, d1 = 0.f, d2 = 0.f, d3 = 0.f;
#pragma unroll
            for (int kt = 0; kt < NKT; kt++) {
                const int brow = (kt * 4 + t) * BSTR + nt * 8 + g;
                float bh = Bhi[brow];
                float bl = Blo[brow];
                mma4(d0, d1, d2, d3, ahi[kt][0], ahi[kt][1], bh);
                mma4(d0, d1, d2, d3, alo[kt][0], alo[kt][1], bh);
                mma4(d0, d1, d2, d3, ahi[kt][0], ahi[kt][1], bl);
            }
            const int R0 = 16 * w + g, R1 = R0 + 8, cb = nt * 8 + 2 * t;
            G[R0 * GSTR + cb] = d0;
            G[R0 * GSTR + cb + 1] = d1;
            G[R1 * GSTR + cb] = d2;
            G[R1 * GSTR + cb + 1] = d3;
        }
        __syncthreads();

        // ---------- activation phase ----------
        // thread handles cells (j = 4w+jj, a = lane + 32*aa), jj,aa in 0..3
#pragma unroll
        for (int aa = 0; aa < 4; aa++) {
#pragma unroll
            for (int jj = 0; jj < 4; jj++) {
                const int j = 4 * w + jj;
                const int a = lane + 32 * aa;
                float gI = G[j * GSTR + a];
                float gF = G[(32 + j) * GSTR + a];
                float gG = G[(64 + j) * GSTR + a];
                float gO = G[(96 + j) * GSTR + a];
                const int ci = aa * 4 + jj;
                float cn = fmaf(sigt(gF), c[ci], sigt(gI) * tanha(gG));
                c[ci] = cn;
                float hv = sigt(gO) * tanha(cn);
                G[j * GSTR + a] = hv;                 // fp32 h (own cell)
                float hh = to_tf32(hv);
                Bhi[j * BSTR + a] = hh;
                Blo[j * BSTR + a] = to_tf32(hv - hh);
            }
        }

        if (IS_DEC) {
            __syncthreads();   // all h written before per-agent projection
            if (tid < 128) {
                const int a = tid;
                float ox = ow[64], oy = ow[65];
#pragma unroll
                for (int k = 0; k < 32; k++) {
                    float hv = G[k * GSTR + a];
                    ox = fmaf(ow[k], hv, ox);
                    oy = fmaf(ow[32 + k], hv, oy);
                }
                out2[(size_t)st * n + base + a] = make_float2(ox, oy);
                float xh = to_tf32(ox);
                Bhi[32 * BSTR + a] = xh; Blo[32 * BSTR + a] = to_tf32(ox - xh);
                float yh = to_tf32(oy);
                Bhi[33 * BSTR + a] = yh; Blo[33 * BSTR + a] = to_tf32(oy - yh);
            }
        } else {
            if (tid < 128 && st + 1 < STEPS) {
                const int a = tid;
                float2 x = __ldg(&rel2[(size_t)(st + 1) * n + base + a]);
                float xh = to_tf32(x.x);
                Bhi[32 * BSTR + a] = xh; Blo[32 * BSTR + a] = to_tf32(x.x - xh);
                float yh = to_tf32(x.y);
                Bhi[33 * BSTR + a] = yh; Blo[33 * BSTR + a] = to_tf32(x.y - yh);
            }
        }
        __syncthreads();
    }

    if (!IS_DEC) {
        // LayerNorm per agent over G rows 0..31; transposed coalesced store
        if (tid < 128) {
            const int a = tid;
            float hv[32];
#pragma unroll
            for (int k = 0; k < 32; k++) hv[k] = G[k * GSTR + a];
            float m = 0.f;
#pragma unroll
            for (int k = 0; k < 32; k++) m += hv[k];
            m *= (1.f / 32.f);
            float var = 0.f;
#pragma unroll
            for (int k = 0; k < 32; k++) { float d = hv[k] - m; var = fmaf(d, d, var); }
            float inv = rsqrtf(var * (1.f / 32.f) + 1e-5f);
#pragma unroll
            for (int k = 0; k < 32; k++)
                g_h[(size_t)k * n + base + a] =
                    fmaf((hv[k] - m) * inv, __ldg(&xg[k]), __ldg(&xb[k]));
        }
    }
}

// ================= K2: attention + context LN + MLP (unchanged, proven) =================
struct AttnSmem {
    float wq[1024], wk[1024], wv[1024], wo[1024];
    float mlp1[4096], mlp2[1536];
    float lncg[64], lncb[64], m1b[64], m2b[24], noi[8];
    float kbuf[8][32][40];
    float vbuf[8][32][40];
};

__device__ __forceinline__ float dot32p(const float *__restrict__ row, const u64 *hp)
{
    const ulonglong2 *wr = (const ulonglong2 *)row;
    u64 acc = 0ULL;
#pragma unroll
    for (int kk = 0; kk < 8; kk++) {
        ulonglong2 w = wr[kk];
        acc = fma2(w.x, hp[2 * kk], acc);
        acc = fma2(w.y, hp[2 * kk + 1], acc);
    }
    return hsum2(acc);
}
__device__ __forceinline__ float dot64p(const float *__restrict__ row, const u64 *hp)
{
    const ulonglong2 *wr = (const ulonglong2 *)row;
    u64 acc = 0ULL;
#pragma unroll
    for (int kk = 0; kk < 16; kk++) {
        ulonglong2 w = wr[kk];
        acc = fma2(w.x, hp[2 * kk], acc);
        acc = fma2(w.y, hp[2 * kk + 1], acc);
    }
    return hsum2(acc);
}

__global__ void __launch_bounds__(256)
k_attn(const float *__restrict__ wq_g, const float *__restrict__ wk_g,
       const float *__restrict__ wv_g, const float *__restrict__ wo_g,
       const float *__restrict__ lncg, const float *__restrict__ lncb,
       const float *__restrict__ m1w, const float *__restrict__ m1b,
       const float *__restrict__ m2w, const float *__restrict__ m2b,
       const float *__restrict__ noi, int n)
{
    extern __shared__ char smem_raw[];
    AttnSmem *s = (AttnSmem *)smem_raw;
    const int tid = threadIdx.x;
#define CP(d, src, c) for (int _i = tid; _i < (c); _i += 256) (d)[_i] = (src)[_i];
    CP(s->wq, wq_g, 1024) CP(s->wk, wk_g, 1024) CP(s->wv, wv_g, 1024) CP(s->wo, wo_g, 1024)
    CP(s->mlp1, m1w, 4096) CP(s->mlp2, m2w, 1536)
    CP(s->lncg, lncg, 64) CP(s->lncb, lncb, 64)
    CP(s->m1b, m1b, 64) CP(s->m2b, m2b, 24) CP(s->noi, noi, 8)
#undef CP
    __syncthreads();

    const int agent = blockIdx.x * 256 + tid;
    if (agent >= n) return;
    const int warp = tid >> 5, lane = tid & 31;

    float hv[32];
#pragma unroll
    for (int k = 0; k < 32; k++) hv[k] = __ldg(&g_h[(size_t)k * n + agent]);
    u64 hp[16];
#pragma unroll
    for (int k = 0; k < 16; k++) hp[k] = pack2(hv[2 * k], hv[2 * k + 1]);

    float q[32];
#pragma unroll
    for (int d = 0; d < 32; d++) {
        q[d] = dot32p(s->wq + d * 32, hp);
        s->kbuf[warp][lane][d] = dot32p(s->wk + d * 32, hp);
        s->vbuf[warp][lane][d] = dot32p(s->wv + d * 32, hp);
    }
    __syncwarp();

    float att[32];
#pragma unroll
    for (int hh = 0; hh < 4; hh++) {
        u64 qp[4];
#pragma unroll
        for (int i = 0; i < 4; i++) qp[i] = pack2(q[hh * 8 + 2 * i], q[hh * 8 + 2 * i + 1]);
        float sc[32], mx = -1e30f;
#pragma unroll
        for (int jj = 0; jj < 32; jj++) {
            const ulonglong2 *kr = (const ulonglong2 *)&s->kbuf[warp][jj][hh * 8];
            ulonglong2 k01 = kr[0], k23 = kr[1];
            u64 acc = fma2(k01.x, qp[0], 0ULL);
            acc = fma2(k01.y, qp[1], acc);
            acc = fma2(k23.x, qp[2], acc);
            acc = fma2(k23.y, qp[3], acc);
            float d0 = hsum2(acc) * 0.35355339059327373f;
            sc[jj] = d0;
            mx = fmaxf(mx, d0);
        }
        float sum = 0.f;
#pragma unroll
        for (int jj = 0; jj < 32; jj++) {
            float e = __expf(sc[jj] - mx);
            sc[jj] = e;
            sum += e;
        }
        float inv = __fdividef(1.f, sum);
        u64 a0 = 0, a1 = 0, a2 = 0, a3 = 0;
#pragma unroll
        for (int jj = 0; jj < 32; jj++) {
            const ulonglong2 *vr = (const ulonglong2 *)&s->vbuf[warp][jj][hh * 8];
            ulonglong2 v01 = vr[0], v23 = vr[1];
            u64 pd = pack2(sc[jj], sc[jj]);
            a0 = fma2(v01.x, pd, a0);
            a1 = fma2(v01.y, pd, a1);
            a2 = fma2(v23.x, pd, a2);
            a3 = fma2(v23.y, pd, a3);
        }
        float2 r0 = unpack2(a0), r1 = unpack2(a1), r2 = unpack2(a2), r3 = unpack2(a3);
        att[hh * 8 + 0] = r0.x * inv; att[hh * 8 + 1] = r0.y * inv;
        att[hh * 8 + 2] = r1.x * inv; att[hh * 8 + 3] = r1.y * inv;
        att[hh * 8 + 4] = r2.x * inv; att[hh * 8 + 5] = r2.y * inv;
        att[hh * 8 + 6] = r3.x * inv; att[hh * 8 + 7] = r3.y * inv;
    }

    u64 ap[16];
#pragma unroll
    for (int k = 0; k < 16; k++) ap[k] = pack2(att[2 * k], att[2 * k + 1]);
    float ctx[64];
#pragma unroll
    for (int jj = 0; jj < 32; jj++) ctx[jj] = hv[jj];
#pragma unroll
    for (int d = 0; d < 32; d++) ctx[32 + d] = dot32p(s->wo + d * 32, ap);

    {
        float m = 0.f;
#pragma unroll
        for (int jj = 0; jj < 64; jj++) m += ctx[jj];
        m *= (1.f / 64.f);
        float v = 0.f;
#pragma unroll
        for (int jj = 0; jj < 64; jj++) { float d = ctx[jj] - m; v = fmaf(d, d, v); }
        float inv = rsqrtf(v * (1.f / 64.f) + 1e-5f);
#pragma unroll
        for (int jj = 0; jj < 64; jj++)
            ctx[jj] = fmaf((ctx[jj] - m) * inv, s->lncg[jj], s->lncb[jj]);
    }

    u64 cp[32];
#pragma unroll
    for (int k = 0; k < 32; k++) cp[k] = pack2(ctx[2 * k], ctx[2 * k + 1]);
    float y1[64];
#pragma unroll
    for (int m = 0; m < 64; m++) {
        float a = dot64p(s->mlp1 + m * 64, cp) + s->m1b[m];
        y1[m] = (a > 0.f) ? a : 0.01f * a;
    }
    u64 yp[32];
#pragma unroll
    for (int k = 0; k < 32; k++) yp[k] = pack2(y1[2 * k], y1[2 * k + 1]);
#pragma unroll
    for (int m = 0; m < 24; m++) {
        float a = dot64p(s->mlp2 + m * 64, yp) + s->m2b[m];
        a = (a > 0.f) ? a : 0.01f * a;
        g_d[(size_t)m * n + agent] = a;
    }
#pragma unroll
    for (int m = 0; m < 8; m++) g_d[(size_t)(24 + m) * n + agent] = s->noi[m];
}

// ================= launch =================
extern "C" void kernel_launch(void *const *d_in, const int *in_sizes, int n_in,
                              void *d_out, int out_size)
{
    const float *rel = (const float *)d_in[1];
    const float *noise = (const float *)d_in[3];
    const float *enc_emb_w = (const float *)d_in[4];
    const float *enc_emb_b = (const float *)d_in[5];
    const float *enc_wih = (const float *)d_in[6];
    const float *enc_whh = (const float *)d_in[7];
    const float *enc_bih = (const float *)d_in[8];
    const float *enc_bhh = (const float *)d_in[9];
    const float *lne_g = (const float *)d_in[10];
    const float *lne_b = (const float *)d_in[11];
    const float *wq = (const float *)d_in[12];
    const float *wk = (const float *)d_in[13];
    const float *wv = (const float *)d_in[14];
    const float *wo = (const float *)d_in[15];
    const float *lnc_g = (const float *)d_in[16];
    const float *lnc_b = (const float *)d_in[17];
    const float *mlp1_w = (const float *)d_in[18];
    const float *mlp1_b = (const float *)d_in[19];
    const float *mlp2_w = (const float *)d_in[20];
    const float *mlp2_b = (const float *)d_in[21];
    const float *dec_emb_w = (const float *)d_in[22];
    const float *dec_emb_b = (const float *)d_in[23];
    const float *dec_wih = (const float *)d_in[24];
    const float *dec_whh = (const float *)d_in[25];
    const float *dec_bih = (const float *)d_in[26];
    const float *dec_bhh = (const float *)d_in[27];
    const float *dec_out_w = (const float *)d_in[28];
    const float *dec_out_b = (const float *)d_in[29];

    int n = in_sizes[1] / (OBS_LEN * 2);

    static bool attr_set = false;
    if (!attr_set) {
        cudaFuncSetAttribute(k_attn, cudaFuncAttributeMaxDynamicSharedMemorySize,
                             (int)sizeof(AttnSmem));
        cudaFuncSetAttribute(k_lstm_mma<OBS_LEN, false>,
                             cudaFuncAttributeMaxDynamicSharedMemorySize, SMEM_MMA);
        cudaFuncSetAttribute(k_lstm_mma<PRED_LEN, true>,
                             cudaFuncAttributeMaxDynamicSharedMemorySize, SMEM_MMA);
        attr_set = true;
    }

    int gridm = n / AG;

    k_lstm_mma<OBS_LEN, false><<<gridm, 256, SMEM_MMA>>>(
        rel, enc_wih, enc_whh, enc_bih, enc_bhh,
        enc_emb_w, enc_emb_b, lne_g, lne_b, nullptr, n);
    k_attn<<<(n + 255) / 256, 256, sizeof(AttnSmem)>>>(
        wq, wk, wv, wo, lnc_g, lnc_b,
        mlp1_w, mlp1_b, mlp2_w, mlp2_b, noise, n);
    k_lstm_mma<PRED_LEN, true><<<gridm, 256, SMEM_MMA>>>(
        rel, dec_wih, dec_whh, dec_bih, dec_bhh,
        dec_emb_w, dec_emb_b, dec_out_w, dec_out_b, (float *)d_out, n);
}

// round 13
// speedup vs baseline: 1.7554x; 1.7554x over previous
#include <cuda_runtime.h>
#include <cuda_bf16.h>
#include <cstdint>

#define OBS_LEN 20
#define PRED_LEN 30
#define MAXN 131072
#define AG 128
#define NKT 3        // k-tiles of 16 (K=48, cols 36..47 zero)
#define BSTR 136     // B pair-array row stride (u32 units) — conflict-free
#define GSTR 136     // gates row stride (floats) — conflict-free

typedef unsigned long long u64;
typedef unsigned int u32;
typedef unsigned short u16;

// ---------------- helpers ----------------
__device__ __forceinline__ u64 fma2(u64 a, u64 b, u64 c) {
    u64 d;
    asm("fma.rn.f32x2 %0, %1, %2, %3;" : "=l"(d) : "l"(a), "l"(b), "l"(c));
    return d;
}
__device__ __forceinline__ u64 pack2(float lo, float hi) {
    u64 d;
    asm("mov.b64 %0, {%1, %2};" : "=l"(d) : "f"(lo), "f"(hi));
    return d;
}
__device__ __forceinline__ float2 unpack2(u64 v) {
    float2 r;
    asm("mov.b64 {%0, %1}, %2;" : "=f"(r.x), "=f"(r.y) : "l"(v));
    return r;
}
__device__ __forceinline__ float hsum2(u64 v) { float2 s = unpack2(v); return s.x + s.y; }
__device__ __forceinline__ float tanha(float x) {
    float r;
    asm("tanh.approx.f32 %0, %1;" : "=f"(r) : "f"(x));
    return r;
}
__device__ __forceinline__ float sigt(float x) { return fmaf(0.5f, tanha(0.5f * x), 0.5f); }

// pack two floats into bf16x2 (v0 -> low half = lower-k element)
__device__ __forceinline__ u32 bf2pack(float v0, float v1) {
    __nv_bfloat162 p = __floats2bfloat162_rn(v0, v1);
    return *(u32 *)&p;
}
__device__ __forceinline__ u16 bf1(float v) {
    __nv_bfloat16 b = __float2bfloat16(v);
    return *(u16 *)&b;
}
__device__ __forceinline__ float bf1f(u16 b) {
    __nv_bfloat16 v = *(__nv_bfloat16 *)&b;
    return __bfloat162float(v);
}

// classic bf16 tensor-core mma (baseline PTX, sm_80+, valid on sm_103)
__device__ __forceinline__ void mma16(float &d0, float &d1, float &d2, float &d3,
                                      u32 a0, u32 a1, u32 a2, u32 a3,
                                      u32 b0, u32 b1)
{
    asm volatile(
        "mma.sync.aligned.m16n8k16.row.col.f32.bf16.bf16.f32 "
        "{%0,%1,%2,%3}, {%4,%5,%6,%7}, {%8,%9}, {%0,%1,%2,%3};"
        : "+f"(d0), "+f"(d1), "+f"(d2), "+f"(d3)
        : "r"(a0), "r"(a1), "r"(a2), "r"(a3), "r"(b0), "r"(b1));
}

// ---------------- scratch ----------------
__device__ float g_h[32 * MAXN];
__device__ float g_d[32 * MAXN];

// smem (float/u32 units):
#define SM_BPHI 0                       // 24*136 u32
#define SM_BPLO (24 * BSTR)             // 24*136 u32
#define SM_G    (2 * 24 * BSTR)         // 128*136 float
#define SM_OW   (SM_G + 128 * GSTR)     // 72
#define SMEM_FLOATS (SM_OW + 72)
#define SMEM_MMA (SMEM_FLOATS * 4)

// ================= MMA LSTM kernel (enc & dec) =================
// xg/xb: enc -> lne_g / lne_b ; dec -> dec_out_w / dec_out_b
template <int STEPS, bool IS_DEC>
__global__ void __launch_bounds__(256, 1)
k_lstm_mma(const float *__restrict__ rel,
           const float *__restrict__ wih, const float *__restrict__ whh,
           const float *__restrict__ bih, const float *__restrict__ bhh,
           const float *__restrict__ embw, const float *__restrict__ embb,
           const float *__restrict__ xg, const float *__restrict__ xb,
           float *__restrict__ out, int n)
{
    extern __shared__ float sm[];
    u32 *Bhi = (u32 *)(sm + SM_BPHI);
    u32 *Blo = (u32 *)(sm + SM_BPLO);
    float *G = sm + SM_G;
    float *ow = sm + SM_OW;

    const int tid = threadIdx.x;
    const int lane = tid & 31;
    const int w = tid >> 5;          // warp 0..7: gate rows [16w, 16w+16)
    const int g = lane >> 2;         // groupID
    const int t = lane & 3;          // threadID in group
    const int base = blockIdx.x * AG;

    // ---- A fragments in regs: bf16x2 hi/lo, per kt: {r0h0, r1h0, r0h1, r1h1} ----
    float wxr[2][3];   // per rsel: w0, w1, bias of row r
#pragma unroll
    for (int rsel = 0; rsel < 2; rsel++) {
        const int r = 16 * w + 8 * rsel + g;
        float w0 = 0.f, w1 = 0.f, b = __ldg(&bih[r]) + __ldg(&bhh[r]);
#pragma unroll
        for (int e = 0; e < 16; e++) {
            float wie = __ldg(&wih[r * 16 + e]);
            w0 = fmaf(wie, __ldg(&embw[e * 2 + 0]), w0);
            w1 = fmaf(wie, __ldg(&embw[e * 2 + 1]), w1);
            b = fmaf(wie, __ldg(&embb[e]), b);
        }
        wxr[rsel][0] = w0; wxr[rsel][1] = w1; wxr[rsel][2] = b;
    }

    u32 ahi[NKT][4], alo[NKT][4];
#pragma unroll
    for (int kt = 0; kt < NKT; kt++) {
#pragma unroll
        for (int half = 0; half < 2; half++) {
#pragma unroll
            for (int rsel = 0; rsel < 2; rsel++) {
                const int r = 16 * w + 8 * rsel + g;
                const int k0 = 16 * kt + 2 * t + 8 * half;
                float v0, v1;
                {
                    int k = k0;
                    v0 = (k < 32) ? __ldg(&whh[r * 32 + k])
                       : (k == 32) ? wxr[rsel][0]
                       : (k == 33) ? wxr[rsel][1]
                       : (k == 34) ? wxr[rsel][2] : 0.f;
                    k = k0 + 1;
                    v1 = (k < 32) ? __ldg(&whh[r * 32 + k])
                       : (k == 32) ? wxr[rsel][0]
                       : (k == 33) ? wxr[rsel][1]
                       : (k == 34) ? wxr[rsel][2] : 0.f;
                }
                float h0 = bf1f(bf1(v0)), h1 = bf1f(bf1(v1));
                ahi[kt][half * 2 + rsel] = bf2pack(v0, v1);
                alo[kt][half * 2 + rsel] = bf2pack(v0 - h0, v1 - h1);
            }
        }
    }

    // ---- init B pair arrays ----
    for (int i = tid; i < 24 * BSTR; i += 256) { Bhi[i] = 0u; Blo[i] = 0u; }
    __syncthreads();

    const float2 *rel2 = (const float2 *)rel;
    float2 *out2 = (float2 *)out;

    if (tid < 128) {
        const int a = tid;
        Bhi[17 * BSTR + a] = bf2pack(1.0f, 0.0f);   // k=34 bias row = 1
        if (IS_DEC) {
#pragma unroll
            for (int kp = 0; kp < 16; kp++) {
                float v0 = g_d[(size_t)(2 * kp) * n + base + a];
                float v1 = g_d[(size_t)(2 * kp + 1) * n + base + a];
                float h0 = bf1f(bf1(v0)), h1 = bf1f(bf1(v1));
                Bhi[kp * BSTR + a] = bf2pack(v0, v1);
                Blo[kp * BSTR + a] = bf2pack(v0 - h0, v1 - h1);
            }
            float2 x = __ldg(&rel2[(size_t)(OBS_LEN - 1) * n + base + a]);
            float h0 = bf1f(bf1(x.x)), h1 = bf1f(bf1(x.y));
            Bhi[16 * BSTR + a] = bf2pack(x.x, x.y);
            Blo[16 * BSTR + a] = bf2pack(x.x - h0, x.y - h1);
        } else {
            float2 x = __ldg(&rel2[base + a]);
            float h0 = bf1f(bf1(x.x)), h1 = bf1f(bf1(x.y));
            Bhi[16 * BSTR + a] = bf2pack(x.x, x.y);
            Blo[16 * BSTR + a] = bf2pack(x.x - h0, x.y - h1);
        }
    }
    if (IS_DEC) {
        if (tid < 64) ow[tid] = __ldg(&xg[tid]);
        if (tid < 2) ow[64 + tid] = __ldg(&xb[tid]);
    }

    float c[16];
#pragma unroll
    for (int i = 0; i < 16; i++) c[i] = 0.f;

    __syncthreads();

#pragma unroll 1
    for (int st = 0; st < STEPS; st++) {
        // ---------- MMA phase: gates[128][128] ----------
#pragma unroll 4
        for (int nt = 0; nt < 16; nt++) {
            float d0 = 0.f, d1 = 0.f, d2 = 0.f, d3 = 0.f;
            const int col = nt * 8 + g;
#pragma unroll
            for (int kt = 0; kt < NKT; kt++) {
                const int r0 = (8 * kt + t) * BSTR + col;
                const int r1 = (8 * kt + t + 4) * BSTR + col;
                u32 bh0 = Bhi[r0], bh1 = Bhi[r1];
                u32 bl0 = Blo[r0], bl1 = Blo[r1];
                mma16(d0, d1, d2, d3,
                      ahi[kt][0], ahi[kt][1], ahi[kt][2], ahi[kt][3], bh0, bh1);
                mma16(d0, d1, d2, d3,
                      alo[kt][0], alo[kt][1], alo[kt][2], alo[kt][3], bh0, bh1);
                mma16(d0, d1, d2, d3,
                      ahi[kt][0], ahi[kt][1], ahi[kt][2], ahi[kt][3], bl0, bl1);
            }
            const int R0 = 16 * w + g, R1 = R0 + 8, cb = nt * 8 + 2 * t;
            G[R0 * GSTR + cb] = d0;
            G[R0 * GSTR + cb + 1] = d1;
            G[R1 * GSTR + cb] = d2;
            G[R1 * GSTR + cb + 1] = d3;
        }
        __syncthreads();

        // ---------- activation phase: cell j=4w+jj, agent a=lane+32aa ----------
#pragma unroll
        for (int aa = 0; aa < 4; aa++) {
#pragma unroll
            for (int jj = 0; jj < 4; jj++) {
                const int j = 4 * w + jj;
                const int a = lane + 32 * aa;
                float gI = G[j * GSTR + a];
                float gF = G[(32 + j) * GSTR + a];
                float gG = G[(64 + j) * GSTR + a];
                float gO = G[(96 + j) * GSTR + a];
                const int ci = aa * 4 + jj;
                float cn = fmaf(sigt(gF), c[ci], sigt(gI) * tanha(gG));
                c[ci] = cn;
                float hv = sigt(gO) * tanha(cn);
                G[j * GSTR + a] = hv;                       // fp32 h
                u16 hh = bf1(hv);
                u16 hl = bf1(hv - bf1f(hh));
                const int pr = j >> 1, hf = j & 1;
                ((u16 *)&Bhi[pr * BSTR + a])[hf] = hh;
                ((u16 *)&Blo[pr * BSTR + a])[hf] = hl;
            }
        }

        if (IS_DEC) {
            __syncthreads();
            if (tid < 128) {
                const int a = tid;
                float ox = ow[64], oy = ow[65];
#pragma unroll
                for (int k = 0; k < 32; k++) {
                    float hv = G[k * GSTR + a];
                    ox = fmaf(ow[k], hv, ox);
                    oy = fmaf(ow[32 + k], hv, oy);
                }
                out2[(size_t)st * n + base + a] = make_float2(ox, oy);
                float h0 = bf1f(bf1(ox)), h1 = bf1f(bf1(oy));
                Bhi[16 * BSTR + a] = bf2pack(ox, oy);
                Blo[16 * BSTR + a] = bf2pack(ox - h0, oy - h1);
            }
        } else {
            if (tid < 128 && st + 1 < STEPS) {
                const int a = tid;
                float2 x = __ldg(&rel2[(size_t)(st + 1) * n + base + a]);
                float h0 = bf1f(bf1(x.x)), h1 = bf1f(bf1(x.y));
                Bhi[16 * BSTR + a] = bf2pack(x.x, x.y);
                Blo[16 * BSTR + a] = bf2pack(x.x - h0, x.y - h1);
            }
        }
        __syncthreads();
    }

    if (!IS_DEC) {
        if (tid < 128) {
            const int a = tid;
            float hv[32];
#pragma unroll
            for (int k = 0; k < 32; k++) hv[k] = G[k * GSTR + a];
            float m = 0.f;
#pragma unroll
            for (int k = 0; k < 32; k++) m += hv[k];
            m *= (1.f / 32.f);
            float var = 0.f;
#pragma unroll
            for (int k = 0; k < 32; k++) { float d = hv[k] - m; var = fmaf(d, d, var); }
            float inv = rsqrtf(var * (1.f / 32.f) + 1e-5f);
#pragma unroll
            for (int k = 0; k < 32; k++)
                g_h[(size_t)k * n + base + a] =
                    fmaf((hv[k] - m) * inv, __ldg(&xg[k]), __ldg(&xb[k]));
        }
    }
}

// ================= K2: attention + context LN + MLP (unchanged, proven) =================
struct AttnSmem {
    float wq[1024], wk[1024], wv[1024], wo[1024];
    float mlp1[4096], mlp2[1536];
    float lncg[64], lncb[64], m1b[64], m2b[24], noi[8];
    float kbuf[8][32][40];
    float vbuf[8][32][40];
};

__device__ __forceinline__ float dot32p(const float *__restrict__ row, const u64 *hp)
{
    const ulonglong2 *wr = (const ulonglong2 *)row;
    u64 acc = 0ULL;
#pragma unroll
    for (int kk = 0; kk < 8; kk++) {
        ulonglong2 w = wr[kk];
        acc = fma2(w.x, hp[2 * kk], acc);
        acc = fma2(w.y, hp[2 * kk + 1], acc);
    }
    return hsum2(acc);
}
__device__ __forceinline__ float dot64p(const float *__restrict__ row, const u64 *hp)
{
    const ulonglong2 *wr = (const ulonglong2 *)row;
    u64 acc = 0ULL;
#pragma unroll
    for (int kk = 0; kk < 16; kk++) {
        ulonglong2 w = wr[kk];
        acc = fma2(w.x, hp[2 * kk], acc);
        acc = fma2(w.y, hp[2 * kk + 1], acc);
    }
    return hsum2(acc);
}

__global__ void __launch_bounds__(256)
k_attn(const float *__restrict__ wq_g, const float *__restrict__ wk_g,
       const float *__restrict__ wv_g, const float *__restrict__ wo_g,
       const float *__restrict__ lncg, const float *__restrict__ lncb,
       const float *__restrict__ m1w, const float *__restrict__ m1b,
       const float *__restrict__ m2w, const float *__restrict__ m2b,
       const float *__restrict__ noi, int n)
{
    extern __shared__ char smem_raw[];
    AttnSmem *s = (AttnSmem *)smem_raw;
    const int tid = threadIdx.x;
#define CP(d, src, c) for (int _i = tid; _i < (c); _i += 256) (d)[_i] = (src)[_i];
    CP(s->wq, wq_g, 1024) CP(s->wk, wk_g, 1024) CP(s->wv, wv_g, 1024) CP(s->wo, wo_g, 1024)
    CP(s->mlp1, m1w, 4096) CP(s->mlp2, m2w, 1536)
    CP(s->lncg, lncg, 64) CP(s->lncb, lncb, 64)
    CP(s->m1b, m1b, 64) CP(s->m2b, m2b, 24) CP(s->noi, noi, 8)
#undef CP
    __syncthreads();

    const int agent = blockIdx.x * 256 + tid;
    if (agent >= n) return;
    const int warp = tid >> 5, lane = tid & 31;

    float hv[32];
#pragma unroll
    for (int k = 0; k < 32; k++) hv[k] = __ldg(&g_h[(size_t)k * n + agent]);
    u64 hp[16];
#pragma unroll
    for (int k = 0; k < 16; k++) hp[k] = pack2(hv[2 * k], hv[2 * k + 1]);

    float q[32];
#pragma unroll
    for (int d = 0; d < 32; d++) {
        q[d] = dot32p(s->wq + d * 32, hp);
        s->kbuf[warp][lane][d] = dot32p(s->wk + d * 32, hp);
        s->vbuf[warp][lane][d] = dot32p(s->wv + d * 32, hp);
    }
    __syncwarp();

    float att[32];
#pragma unroll
    for (int hh = 0; hh < 4; hh++) {
        u64 qp[4];
#pragma unroll
        for (int i = 0; i < 4; i++) qp[i] = pack2(q[hh * 8 + 2 * i], q[hh * 8 + 2 * i + 1]);
        float sc[32], mx = -1e30f;
#pragma unroll
        for (int jj = 0; jj < 32; jj++) {
            const ulonglong2 *kr = (const ulonglong2 *)&s->kbuf[warp][jj][hh * 8];
            ulonglong2 k01 = kr[0], k23 = kr[1];
            u64 acc = fma2(k01.x, qp[0], 0ULL);
            acc = fma2(k01.y, qp[1], acc);
            acc = fma2(k23.x, qp[2], acc);
            acc = fma2(k23.y, qp[3], acc);
            float d0 = hsum2(acc) * 0.35355339059327373f;
            sc[jj] = d0;
            mx = fmaxf(mx, d0);
        }
        float sum = 0.f;
#pragma unroll
        for (int jj = 0; jj < 32; jj++) {
            float e = __expf(sc[jj] - mx);
            sc[jj] = e;
            sum += e;
        }
        float inv = __fdividef(1.f, sum);
        u64 a0 = 0, a1 = 0, a2 = 0, a3 = 0;
#pragma unroll
        for (int jj = 0; jj < 32; jj++) {
            const ulonglong2 *vr = (const ulonglong2 *)&s->vbuf[warp][jj][hh * 8];
            ulonglong2 v01 = vr[0], v23 = vr[1];
            u64 pd = pack2(sc[jj], sc[jj]);
            a0 = fma2(v01.x, pd, a0);
            a1 = fma2(v01.y, pd, a1);
            a2 = fma2(v23.x, pd, a2);
            a3 = fma2(v23.y, pd, a3);
        }
        float2 r0 = unpack2(a0), r1 = unpack2(a1), r2 = unpack2(a2), r3 = unpack2(a3);
        att[hh * 8 + 0] = r0.x * inv; att[hh * 8 + 1] = r0.y * inv;
        att[hh * 8 + 2] = r1.x * inv; att[hh * 8 + 3] = r1.y * inv;
        att[hh * 8 + 4] = r2.x * inv; att[hh * 8 + 5] = r2.y * inv;
        att[hh * 8 + 6] = r3.x * inv; att[hh * 8 + 7] = r3.y * inv;
    }

    u64 ap[16];
#pragma unroll
    for (int k = 0; k < 16; k++) ap[k] = pack2(att[2 * k], att[2 * k + 1]);
    float ctx[64];
#pragma unroll
    for (int jj = 0; jj < 32; jj++) ctx[jj] = hv[jj];
#pragma unroll
    for (int d = 0; d < 32; d++) ctx[32 + d] = dot32p(s->wo + d * 32, ap);

    {
        float m = 0.f;
#pragma unroll
        for (int jj = 0; jj < 64; jj++) m += ctx[jj];
        m *= (1.f / 64.f);
        float v = 0.f;
#pragma unroll
        for (int jj = 0; jj < 64; jj++) { float d = ctx[jj] - m; v = fmaf(d, d, v); }
        float inv = rsqrtf(v * (1.f / 64.f) + 1e-5f);
#pragma unroll
        for (int jj = 0; jj < 64; jj++)
            ctx[jj] = fmaf((ctx[jj] - m) * inv, s->lncg[jj], s->lncb[jj]);
    }

    u64 cp[32];
#pragma unroll
    for (int k = 0; k < 32; k++) cp[k] = pack2(ctx[2 * k], ctx[2 * k + 1]);
    float y1[64];
#pragma unroll
    for (int m = 0; m < 64; m++) {
        float a = dot64p(s->mlp1 + m * 64, cp) + s->m1b[m];
        y1[m] = (a > 0.f) ? a : 0.01f * a;
    }
    u64 yp[32];
#pragma unroll
    for (int k = 0; k < 32; k++) yp[k] = pack2(y1[2 * k], y1[2 * k + 1]);
#pragma unroll
    for (int m = 0; m < 24; m++) {
        float a = dot64p(s->mlp2 + m * 64, yp) + s->m2b[m];
        a = (a > 0.f) ? a : 0.01f * a;
        g_d[(size_t)m * n + agent] = a;
    }
#pragma unroll
    for (int m = 0; m < 8; m++) g_d[(size_t)(24 + m) * n + agent] = s->noi[m];
}

// ================= launch =================
extern "C" void kernel_launch(void *const *d_in, const int *in_sizes, int n_in,
                              void *d_out, int out_size)
{
    const float *rel = (const float *)d_in[1];
    const float *noise = (const float *)d_in[3];
    const float *enc_emb_w = (const float *)d_in[4];
    const float *enc_emb_b = (const float *)d_in[5];
    const float *enc_wih = (const float *)d_in[6];
    const float *enc_whh = (const float *)d_in[7];
    const float *enc_bih = (const float *)d_in[8];
    const float *enc_bhh = (const float *)d_in[9];
    const float *lne_g = (const float *)d_in[10];
    const float *lne_b = (const float *)d_in[11];
    const float *wq = (const float *)d_in[12];
    const float *wk = (const float *)d_in[13];
    const float *wv = (const float *)d_in[14];
    const float *wo = (const float *)d_in[15];
    const float *lnc_g = (const float *)d_in[16];
    const float *lnc_b = (const float *)d_in[17];
    const float *mlp1_w = (const float *)d_in[18];
    const float *mlp1_b = (const float *)d_in[19];
    const float *mlp2_w = (const float *)d_in[20];
    const float *mlp2_b = (const float *)d_in[21];
    const float *dec_emb_w = (const float *)d_in[22];
    const float *dec_emb_b = (const float *)d_in[23];
    const float *dec_wih = (const float *)d_in[24];
    const float *dec_whh = (const float *)d_in[25];
    const float *dec_bih = (const float *)d_in[26];
    const float *dec_bhh = (const float *)d_in[27];
    const float *dec_out_w = (const float *)d_in[28];
    const float *dec_out_b = (const float *)d_in[29];

    int n = in_sizes[1] / (OBS_LEN * 2);

    static bool attr_set = false;
    if (!attr_set) {
        cudaFuncSetAttribute(k_attn, cudaFuncAttributeMaxDynamicSharedMemorySize,
                             (int)sizeof(AttnSmem));
        cudaFuncSetAttribute(k_lstm_mma<OBS_LEN, false>,
                             cudaFuncAttributeMaxDynamicSharedMemorySize, SMEM_MMA);
        cudaFuncSetAttribute(k_lstm_mma<PRED_LEN, true>,
                             cudaFuncAttributeMaxDynamicSharedMemorySize, SMEM_MMA);
        attr_set = true;
    }

    int gridm = n / AG;

    k_lstm_mma<OBS_LEN, false><<<gridm, 256, SMEM_MMA>>>(
        rel, enc_wih, enc_whh, enc_bih, enc_bhh,
        enc_emb_w, enc_emb_b, lne_g, lne_b, nullptr, n);
    k_attn<<<(n + 255) / 256, 256, sizeof(AttnSmem)>>>(
        wq, wk, wv, wo, lnc_g, lnc_b,
        mlp1_w, mlp1_b, mlp2_w, mlp2_b, noise, n);
    k_lstm_mma<PRED_LEN, true><<<gridm, 256, SMEM_MMA>>>(
        rel, dec_wih, dec_whh, dec_bih, dec_bhh,
        dec_emb_w, dec_emb_b, dec_out_w, dec_out_b, (float *)d_out, n);
}

// round 14
// speedup vs baseline: 1.7580x; 1.0015x over previous
#include <cuda_runtime.h>
#include <cuda_bf16.h>
#include <cstdint>

#define OBS_LEN 20
#define PRED_LEN 30
#define MAXN 131072
#define AG 128
#define NKT 3        // k-tiles of 16 (K=48, cols 36..47 zero)
#define BSTR 136     // B pair-array row stride (u32 units) — conflict-free
#define GSTR 136     // gates row stride (floats) — conflict-free

typedef unsigned long long u64;
typedef unsigned int u32;
typedef unsigned short u16;

// ---------------- helpers ----------------
__device__ __forceinline__ u64 fma2(u64 a, u64 b, u64 c) {
    u64 d;
    asm("fma.rn.f32x2 %0, %1, %2, %3;" : "=l"(d) : "l"(a), "l"(b), "l"(c));
    return d;
}
__device__ __forceinline__ u64 pack2(float lo, float hi) {
    u64 d;
    asm("mov.b64 %0, {%1, %2};" : "=l"(d) : "f"(lo), "f"(hi));
    return d;
}
__device__ __forceinline__ float2 unpack2(u64 v) {
    float2 r;
    asm("mov.b64 {%0, %1}, %2;" : "=f"(r.x), "=f"(r.y) : "l"(v));
    return r;
}
__device__ __forceinline__ float hsum2(u64 v) { float2 s = unpack2(v); return s.x + s.y; }
__device__ __forceinline__ float tanha(float x) {
    float r;
    asm("tanh.approx.f32 %0, %1;" : "=f"(r) : "f"(x));
    return r;
}
__device__ __forceinline__ float sigt(float x) { return fmaf(0.5f, tanha(0.5f * x), 0.5f); }

// pack two floats into bf16x2 (v0 -> low half = lower-k element)
__device__ __forceinline__ u32 bf2pack(float v0, float v1) {
    __nv_bfloat162 p = __floats2bfloat162_rn(v0, v1);
    return *(u32 *)&p;
}
__device__ __forceinline__ u16 bf1(float v) {
    __nv_bfloat16 b = __float2bfloat16(v);
    return *(u16 *)&b;
}
__device__ __forceinline__ float bf1f(u16 b) {
    __nv_bfloat16 v = *(__nv_bfloat16 *)&b;
    return __bfloat162float(v);
}

// classic bf16 tensor-core mma (baseline PTX, sm_80+, valid on sm_103)
__device__ __forceinline__ void mma16(float &d0, float &d1, float &d2, float &d3,
                                      u32 a0, u32 a1, u32 a2, u32 a3,
                                      u32 b0, u32 b1)
{
    asm volatile(
        "mma.sync.aligned.m16n8k16.row.col.f32.bf16.bf16.f32 "
        "{%0,%1,%2,%3}, {%4,%5,%6,%7}, {%8,%9}, {%0,%1,%2,%3};"
        : "+f"(d0), "+f"(d1), "+f"(d2), "+f"(d3)
        : "r"(a0), "r"(a1), "r"(a2), "r"(a3), "r"(b0), "r"(b1));
}

// ---------------- scratch ----------------
__device__ float g_h[32 * MAXN];
__device__ float g_d[32 * MAXN];

// smem (float/u32 units):
#define SM_BPHI 0                       // 24*136 u32
#define SM_BPLO (24 * BSTR)             // 24*136 u32
#define SM_G    (2 * 24 * BSTR)         // 128*136 float
#define SM_OW   (SM_G + 128 * GSTR)     // 72
#define SMEM_FLOATS (SM_OW + 72)
#define SMEM_MMA (SMEM_FLOATS * 4)

// ================= MMA LSTM kernel (enc & dec) =================
// xg/xb: enc -> lne_g / lne_b ; dec -> dec_out_w / dec_out_b
template <int STEPS, bool IS_DEC>
__global__ void __launch_bounds__(256, 2)
k_lstm_mma(const float *__restrict__ rel,
           const float *__restrict__ wih, const float *__restrict__ whh,
           const float *__restrict__ bih, const float *__restrict__ bhh,
           const float *__restrict__ embw, const float *__restrict__ embb,
           const float *__restrict__ xg, const float *__restrict__ xb,
           float *__restrict__ out, int n)
{
    extern __shared__ float sm[];
    u32 *Bhi = (u32 *)(sm + SM_BPHI);
    u32 *Blo = (u32 *)(sm + SM_BPLO);
    float *G = sm + SM_G;
    float *ow = sm + SM_OW;

    const int tid = threadIdx.x;
    const int lane = tid & 31;
    const int w = tid >> 5;          // warp 0..7: gate rows [16w, 16w+16)
    const int g = lane >> 2;         // groupID
    const int t = lane & 3;          // threadID in group
    const int base = blockIdx.x * AG;

    // ---- A fragments in regs: bf16x2 hi/lo, per kt: {r0h0, r1h0, r0h1, r1h1} ----
    float wxr[2][3];   // per rsel: w0, w1, bias of row r
#pragma unroll
    for (int rsel = 0; rsel < 2; rsel++) {
        const int r = 16 * w + 8 * rsel + g;
        float w0 = 0.f, w1 = 0.f, b = __ldg(&bih[r]) + __ldg(&bhh[r]);
#pragma unroll
        for (int e = 0; e < 16; e++) {
            float wie = __ldg(&wih[r * 16 + e]);
            w0 = fmaf(wie, __ldg(&embw[e * 2 + 0]), w0);
            w1 = fmaf(wie, __ldg(&embw[e * 2 + 1]), w1);
            b = fmaf(wie, __ldg(&embb[e]), b);
        }
        wxr[rsel][0] = w0; wxr[rsel][1] = w1; wxr[rsel][2] = b;
    }

    u32 ahi[NKT][4], alo[NKT][4];
#pragma unroll
    for (int kt = 0; kt < NKT; kt++) {
#pragma unroll
        for (int half = 0; half < 2; half++) {
#pragma unroll
            for (int rsel = 0; rsel < 2; rsel++) {
                const int r = 16 * w + 8 * rsel + g;
                const int k0 = 16 * kt + 2 * t + 8 * half;
                float v0, v1;
                {
                    int k = k0;
                    v0 = (k < 32) ? __ldg(&whh[r * 32 + k])
                       : (k == 32) ? wxr[rsel][0]
                       : (k == 33) ? wxr[rsel][1]
                       : (k == 34) ? wxr[rsel][2] : 0.f;
                    k = k0 + 1;
                    v1 = (k < 32) ? __ldg(&whh[r * 32 + k])
                       : (k == 32) ? wxr[rsel][0]
                       : (k == 33) ? wxr[rsel][1]
                       : (k == 34) ? wxr[rsel][2] : 0.f;
                }
                float h0 = bf1f(bf1(v0)), h1 = bf1f(bf1(v1));
                ahi[kt][half * 2 + rsel] = bf2pack(v0, v1);
                alo[kt][half * 2 + rsel] = bf2pack(v0 - h0, v1 - h1);
            }
        }
    }

    // ---- init B pair arrays ----
    for (int i = tid; i < 24 * BSTR; i += 256) { Bhi[i] = 0u; Blo[i] = 0u; }
    __syncthreads();

    const float2 *rel2 = (const float2 *)rel;
    float2 *out2 = (float2 *)out;

    if (tid < 128) {
        const int a = tid;
        Bhi[17 * BSTR + a] = bf2pack(1.0f, 0.0f);   // k=34 bias row = 1
        if (IS_DEC) {
#pragma unroll
            for (int kp = 0; kp < 16; kp++) {
                float v0 = g_d[(size_t)(2 * kp) * n + base + a];
                float v1 = g_d[(size_t)(2 * kp + 1) * n + base + a];
                float h0 = bf1f(bf1(v0)), h1 = bf1f(bf1(v1));
                Bhi[kp * BSTR + a] = bf2pack(v0, v1);
                Blo[kp * BSTR + a] = bf2pack(v0 - h0, v1 - h1);
            }
            float2 x = __ldg(&rel2[(size_t)(OBS_LEN - 1) * n + base + a]);
            float h0 = bf1f(bf1(x.x)), h1 = bf1f(bf1(x.y));
            Bhi[16 * BSTR + a] = bf2pack(x.x, x.y);
            Blo[16 * BSTR + a] = bf2pack(x.x - h0, x.y - h1);
        } else {
            float2 x = __ldg(&rel2[base + a]);
            float h0 = bf1f(bf1(x.x)), h1 = bf1f(bf1(x.y));
            Bhi[16 * BSTR + a] = bf2pack(x.x, x.y);
            Blo[16 * BSTR + a] = bf2pack(x.x - h0, x.y - h1);
        }
    }
    if (IS_DEC) {
        if (tid < 64) ow[tid] = __ldg(&xg[tid]);
        if (tid < 2) ow[64 + tid] = __ldg(&xb[tid]);
    }

    float c[16];
#pragma unroll
    for (int i = 0; i < 16; i++) c[i] = 0.f;

    __syncthreads();

#pragma unroll 1
    for (int st = 0; st < STEPS; st++) {
        // ---------- MMA phase: gates[128][128] ----------
#pragma unroll 4
        for (int nt = 0; nt < 16; nt++) {
            float d0 = 0.f, d1 = 0.f, d2 = 0.f, d3 = 0.f;
            const int col = nt * 8 + g;
#pragma unroll
            for (int kt = 0; kt < NKT; kt++) {
                const int r0 = (8 * kt + t) * BSTR + col;
                const int r1 = (8 * kt + t + 4) * BSTR + col;
                u32 bh0 = Bhi[r0], bh1 = Bhi[r1];
                u32 bl0 = Blo[r0], bl1 = Blo[r1];
                mma16(d0, d1, d2, d3,
                      ahi[kt][0], ahi[kt][1], ahi[kt][2], ahi[kt][3], bh0, bh1);
                mma16(d0, d1, d2, d3,
                      alo[kt][0], alo[kt][1], alo[kt][2], alo[kt][3], bh0, bh1);
                mma16(d0, d1, d2, d3,
                      ahi[kt][0], ahi[kt][1], ahi[kt][2], ahi[kt][3], bl0, bl1);
            }
            const int R0 = 16 * w + g, R1 = R0 + 8, cb = nt * 8 + 2 * t;
            G[R0 * GSTR + cb] = d0;
            G[R0 * GSTR + cb + 1] = d1;
            G[R1 * GSTR + cb] = d2;
            G[R1 * GSTR + cb + 1] = d3;
        }
        __syncthreads();

        // ---------- activation phase: cell j=4w+jj, agent a=lane+32aa ----------
#pragma unroll
        for (int aa = 0; aa < 4; aa++) {
#pragma unroll
            for (int jj = 0; jj < 4; jj++) {
                const int j = 4 * w + jj;
                const int a = lane + 32 * aa;
                float gI = G[j * GSTR + a];
                float gF = G[(32 + j) * GSTR + a];
                float gG = G[(64 + j) * GSTR + a];
                float gO = G[(96 + j) * GSTR + a];
                const int ci = aa * 4 + jj;
                float cn = fmaf(sigt(gF), c[ci], sigt(gI) * tanha(gG));
                c[ci] = cn;
                float hv = sigt(gO) * tanha(cn);
                G[j * GSTR + a] = hv;                       // fp32 h
                u16 hh = bf1(hv);
                u16 hl = bf1(hv - bf1f(hh));
                const int pr = j >> 1, hf = j & 1;
                ((u16 *)&Bhi[pr * BSTR + a])[hf] = hh;
                ((u16 *)&Blo[pr * BSTR + a])[hf] = hl;
            }
        }

        if (IS_DEC) {
            __syncthreads();
            if (tid < 128) {
                const int a = tid;
                float ox = ow[64], oy = ow[65];
#pragma unroll
                for (int k = 0; k < 32; k++) {
                    float hv = G[k * GSTR + a];
                    ox = fmaf(ow[k], hv, ox);
                    oy = fmaf(ow[32 + k], hv, oy);
                }
                out2[(size_t)st * n + base + a] = make_float2(ox, oy);
                float h0 = bf1f(bf1(ox)), h1 = bf1f(bf1(oy));
                Bhi[16 * BSTR + a] = bf2pack(ox, oy);
                Blo[16 * BSTR + a] = bf2pack(ox - h0, oy - h1);
            }
        } else {
            if (tid < 128 && st + 1 < STEPS) {
                const int a = tid;
                float2 x = __ldg(&rel2[(size_t)(st + 1) * n + base + a]);
                float h0 = bf1f(bf1(x.x)), h1 = bf1f(bf1(x.y));
                Bhi[16 * BSTR + a] = bf2pack(x.x, x.y);
                Blo[16 * BSTR + a] = bf2pack(x.x - h0, x.y - h1);
            }
        }
        __syncthreads();
    }

    if (!IS_DEC) {
        if (tid < 128) {
            const int a = tid;
            float hv[32];
#pragma unroll
            for (int k = 0; k < 32; k++) hv[k] = G[k * GSTR + a];
            float m = 0.f;
#pragma unroll
            for (int k = 0; k < 32; k++) m += hv[k];
            m *= (1.f / 32.f);
            float var = 0.f;
#pragma unroll
            for (int k = 0; k < 32; k++) { float d = hv[k] - m; var = fmaf(d, d, var); }
            float inv = rsqrtf(var * (1.f / 32.f) + 1e-5f);
#pragma unroll
            for (int k = 0; k < 32; k++)
                g_h[(size_t)k * n + base + a] =
                    fmaf((hv[k] - m) * inv, __ldg(&xg[k]), __ldg(&xb[k]));
        }
    }
}

// ================= K2: attention + context LN + MLP (unchanged, proven) =================
struct AttnSmem {
    float wq[1024], wk[1024], wv[1024], wo[1024];
    float mlp1[4096], mlp2[1536];
    float lncg[64], lncb[64], m1b[64], m2b[24], noi[8];
    float kbuf[8][32][40];
    float vbuf[8][32][40];
};

__device__ __forceinline__ float dot32p(const float *__restrict__ row, const u64 *hp)
{
    const ulonglong2 *wr = (const ulonglong2 *)row;
    u64 acc = 0ULL;
#pragma unroll
    for (int kk = 0; kk < 8; kk++) {
        ulonglong2 w = wr[kk];
        acc = fma2(w.x, hp[2 * kk], acc);
        acc = fma2(w.y, hp[2 * kk + 1], acc);
    }
    return hsum2(acc);
}
__device__ __forceinline__ float dot64p(const float *__restrict__ row, const u64 *hp)
{
    const ulonglong2 *wr = (const ulonglong2 *)row;
    u64 acc = 0ULL;
#pragma unroll
    for (int kk = 0; kk < 16; kk++) {
        ulonglong2 w = wr[kk];
        acc = fma2(w.x, hp[2 * kk], acc);
        acc = fma2(w.y, hp[2 * kk + 1], acc);
    }
    return hsum2(acc);
}

__global__ void __launch_bounds__(256)
k_attn(const float *__restrict__ wq_g, const float *__restrict__ wk_g,
       const float *__restrict__ wv_g, const float *__restrict__ wo_g,
       const float *__restrict__ lncg, const float *__restrict__ lncb,
       const float *__restrict__ m1w, const float *__restrict__ m1b,
       const float *__restrict__ m2w, const float *__restrict__ m2b,
       const float *__restrict__ noi, int n)
{
    extern __shared__ char smem_raw[];
    AttnSmem *s = (AttnSmem *)smem_raw;
    const int tid = threadIdx.x;
#define CP(d, src, c) for (int _i = tid; _i < (c); _i += 256) (d)[_i] = (src)[_i];
    CP(s->wq, wq_g, 1024) CP(s->wk, wk_g, 1024) CP(s->wv, wv_g, 1024) CP(s->wo, wo_g, 1024)
    CP(s->mlp1, m1w, 4096) CP(s->mlp2, m2w, 1536)
    CP(s->lncg, lncg, 64) CP(s->lncb, lncb, 64)
    CP(s->m1b, m1b, 64) CP(s->m2b, m2b, 24) CP(s->noi, noi, 8)
#undef CP
    __syncthreads();

    const int agent = blockIdx.x * 256 + tid;
    if (agent >= n) return;
    const int warp = tid >> 5, lane = tid & 31;

    float hv[32];
#pragma unroll
    for (int k = 0; k < 32; k++) hv[k] = __ldg(&g_h[(size_t)k * n + agent]);
    u64 hp[16];
#pragma unroll
    for (int k = 0; k < 16; k++) hp[k] = pack2(hv[2 * k], hv[2 * k + 1]);

    float q[32];
#pragma unroll
    for (int d = 0; d < 32; d++) {
        q[d] = dot32p(s->wq + d * 32, hp);
        s->kbuf[warp][lane][d] = dot32p(s->wk + d * 32, hp);
        s->vbuf[warp][lane][d] = dot32p(s->wv + d * 32, hp);
    }
    __syncwarp();

    float att[32];
#pragma unroll
    for (int hh = 0; hh < 4; hh++) {
        u64 qp[4];
#pragma unroll
        for (int i = 0; i < 4; i++) qp[i] = pack2(q[hh * 8 + 2 * i], q[hh * 8 + 2 * i + 1]);
        float sc[32], mx = -1e30f;
#pragma unroll
        for (int jj = 0; jj < 32; jj++) {
            const ulonglong2 *kr = (const ulonglong2 *)&s->kbuf[warp][jj][hh * 8];
            ulonglong2 k01 = kr[0], k23 = kr[1];
            u64 acc = fma2(k01.x, qp[0], 0ULL);
            acc = fma2(k01.y, qp[1], acc);
            acc = fma2(k23.x, qp[2], acc);
            acc = fma2(k23.y, qp[3], acc);
            float d0 = hsum2(acc) * 0.35355339059327373f;
            sc[jj] = d0;
            mx = fmaxf(mx, d0);
        }
        float sum = 0.f;
#pragma unroll
        for (int jj = 0; jj < 32; jj++) {
            float e = __expf(sc[jj] - mx);
            sc[jj] = e;
            sum += e;
        }
        float inv = __fdividef(1.f, sum);
        u64 a0 = 0, a1 = 0, a2 = 0, a3 = 0;
#pragma unroll
        for (int jj = 0; jj < 32; jj++) {
            const ulonglong2 *vr = (const ulonglong2 *)&s->vbuf[warp][jj][hh * 8];
            ulonglong2 v01 = vr[0], v23 = vr[1];
            u64 pd = pack2(sc[jj], sc[jj]);
            a0 = fma2(v01.x, pd, a0);
            a1 = fma2(v01.y, pd, a1);
            a2 = fma2(v23.x, pd, a2);
            a3 = fma2(v23.y, pd, a3);
        }
        float2 r0 = unpack2(a0), r1 = unpack2(a1), r2 = unpack2(a2), r3 = unpack2(a3);
        att[hh * 8 + 0] = r0.x * inv; att[hh * 8 + 1] = r0.y * inv;
        att[hh * 8 + 2] = r1.x * inv; att[hh * 8 + 3] = r1.y * inv;
        att[hh * 8 + 4] = r2.x * inv; att[hh * 8 + 5] = r2.y * inv;
        att[hh * 8 + 6] = r3.x * inv; att[hh * 8 + 7] = r3.y * inv;
    }

    u64 ap[16];
#pragma unroll
    for (int k = 0; k < 16; k++) ap[k] = pack2(att[2 * k], att[2 * k + 1]);
    float ctx[64];
#pragma unroll
    for (int jj = 0; jj < 32; jj++) ctx[jj] = hv[jj];
#pragma unroll
    for (int d = 0; d < 32; d++) ctx[32 + d] = dot32p(s->wo + d * 32, ap);

    {
        float m = 0.f;
#pragma unroll
        for (int jj = 0; jj < 64; jj++) m += ctx[jj];
        m *= (1.f / 64.f);
        float v = 0.f;
#pragma unroll
        for (int jj = 0; jj < 64; jj++) { float d = ctx[jj] - m; v = fmaf(d, d, v); }
        float inv = rsqrtf(v * (1.f / 64.f) + 1e-5f);
#pragma unroll
        for (int jj = 0; jj < 64; jj++)
            ctx[jj] = fmaf((ctx[jj] - m) * inv, s->lncg[jj], s->lncb[jj]);
    }

    u64 cp[32];
#pragma unroll
    for (int k = 0; k < 32; k++) cp[k] = pack2(ctx[2 * k], ctx[2 * k + 1]);
    float y1[64];
#pragma unroll
    for (int m = 0; m < 64; m++) {
        float a = dot64p(s->mlp1 + m * 64, cp) + s->m1b[m];
        y1[m] = (a > 0.f) ? a : 0.01f * a;
    }
    u64 yp[32];
#pragma unroll
    for (int k = 0; k < 32; k++) yp[k] = pack2(y1[2 * k], y1[2 * k + 1]);
#pragma unroll
    for (int m = 0; m < 24; m++) {
        float a = dot64p(s->mlp2 + m * 64, yp) + s->m2b[m];
        a = (a > 0.f) ? a : 0.01f * a;
        g_d[(size_t)m * n + agent] = a;
    }
#pragma unroll
    for (int m = 0; m < 8; m++) g_d[(size_t)(24 + m) * n + agent] = s->noi[m];
}

// ================= launch =================
extern "C" void kernel_launch(void *const *d_in, const int *in_sizes, int n_in,
                              void *d_out, int out_size)
{
    const float *rel = (const float *)d_in[1];
    const float *noise = (const float *)d_in[3];
    const float *enc_emb_w = (const float *)d_in[4];
    const float *enc_emb_b = (const float *)d_in[5];
    const float *enc_wih = (const float *)d_in[6];
    const float *enc_whh = (const float *)d_in[7];
    const float *enc_bih = (const float *)d_in[8];
    const float *enc_bhh = (const float *)d_in[9];
    const float *lne_g = (const float *)d_in[10];
    const float *lne_b = (const float *)d_in[11];
    const float *wq = (const float *)d_in[12];
    const float *wk = (const float *)d_in[13];
    const float *wv = (const float *)d_in[14];
    const float *wo = (const float *)d_in[15];
    const float *lnc_g = (const float *)d_in[16];
    const float *lnc_b = (const float *)d_in[17];
    const float *mlp1_w = (const float *)d_in[18];
    const float *mlp1_b = (const float *)d_in[19];
    const float *mlp2_w = (const float *)d_in[20];
    const float *mlp2_b = (const float *)d_in[21];
    const float *dec_emb_w = (const float *)d_in[22];
    const float *dec_emb_b = (const float *)d_in[23];
    const float *dec_wih = (const float *)d_in[24];
    const float *dec_whh = (const float *)d_in[25];
    const float *dec_bih = (const float *)d_in[26];
    const float *dec_bhh = (const float *)d_in[27];
    const float *dec_out_w = (const float *)d_in[28];
    const float *dec_out_b = (const float *)d_in[29];

    int n = in_sizes[1] / (OBS_LEN * 2);

    static bool attr_set = false;
    if (!attr_set) {
        cudaFuncSetAttribute(k_attn, cudaFuncAttributeMaxDynamicSharedMemorySize,
                             (int)sizeof(AttnSmem));
        cudaFuncSetAttribute(k_lstm_mma<OBS_LEN, false>,
                             cudaFuncAttributeMaxDynamicSharedMemorySize, SMEM_MMA);
        cudaFuncSetAttribute(k_lstm_mma<PRED_LEN, true>,
                             cudaFuncAttributeMaxDynamicSharedMemorySize, SMEM_MMA);
        // ask for the full shared-memory carveout so TWO 96KB CTAs co-reside
        cudaFuncSetAttribute(k_lstm_mma<OBS_LEN, false>,
                             cudaFuncAttributePreferredSharedMemoryCarveout,
                             cudaSharedmemCarveoutMaxShared);
        cudaFuncSetAttribute(k_lstm_mma<PRED_LEN, true>,
                             cudaFuncAttributePreferredSharedMemoryCarveout,
                             cudaSharedmemCarveoutMaxShared);
        attr_set = true;
    }

    int gridm = n / AG;

    k_lstm_mma<OBS_LEN, false><<<gridm, 256, SMEM_MMA>>>(
        rel, enc_wih, enc_whh, enc_bih, enc_bhh,
        enc_emb_w, enc_emb_b, lne_g, lne_b, nullptr, n);
    k_attn<<<(n + 255) / 256, 256, sizeof(AttnSmem)>>>(
        wq, wk, wv, wo, lnc_g, lnc_b,
        mlp1_w, mlp1_b, mlp2_w, mlp2_b, noise, n);
    k_lstm_mma<PRED_LEN, true><<<gridm, 256, SMEM_MMA>>>(
        rel, dec_wih, dec_whh, dec_bih, dec_bhh,
        dec_emb_w, dec_emb_b, dec_out_w, dec_out_b, (float *)d_out, n);
}